// round 2
// baseline (speedup 1.0000x reference)
#include <cuda_runtime.h>
#include <cuda_bf16.h>
#include <stdint.h>

// Problem dims
#define Bb   32
#define Ss   2048
#define Ee   1024
#define Uu   1024
#define TOK  (Bb * Ss)          // 65536 tokens

// GEMM tiling
#define TM   128                 // tokens per CTA
#define TN   256                 // U columns per n-chunk
#define KT   32                  // K tile (bf16 elements)
#define NCH  (Uu / TN)           // 4
#define NKT  (Ee / KT)           // 32

// Padded smem rows: 32 data halfs + 8 pad = 40 halfs = 80 bytes (conflict-free ldmatrix)
#define ROWB 80

// smem byte offsets within one stage
#define SM_A_HI 0
#define SM_A_LO (TM * ROWB)                  // 10240
#define SM_B_HI (2 * TM * ROWB)              // 20480
#define SM_B_LO (2 * TM * ROWB + TN * ROWB)  // 40960
#define STAGE   (2 * TM * ROWB + 2 * TN * ROWB)  // 61440
#define SMEM_DYN (2 * STAGE)                 // 122880

// ------------------------- device scratch -------------------------
__device__ __nv_bfloat16 g_Mhi[Uu * Ee];
__device__ __nv_bfloat16 g_Mlo[Uu * Ee];
__device__ float g_score[TOK];
__device__ float g_alpha[TOK];

// ------------------------- helpers -------------------------
__device__ __forceinline__ uint32_t smem_u32(const void* p) {
    uint32_t a;
    asm("{ .reg .u64 t; cvta.to.shared.u64 t, %1; cvt.u32.u64 %0, t; }"
        : "=r"(a) : "l"(p));
    return a;
}

__device__ __forceinline__ void cp_async16(uint32_t dst_smem, const void* src) {
    asm volatile("cp.async.ca.shared.global [%0], [%1], 16;"
                 :: "r"(dst_smem), "l"(src) : "memory");
}
__device__ __forceinline__ void cp_commit() {
    asm volatile("cp.async.commit_group;" ::: "memory");
}

__device__ __forceinline__ void ldsm_x4(uint32_t* r, uint32_t addr) {
    asm volatile("ldmatrix.sync.aligned.m8n8.x4.shared.b16 {%0,%1,%2,%3}, [%4];"
                 : "=r"(r[0]), "=r"(r[1]), "=r"(r[2]), "=r"(r[3]) : "r"(addr));
}

__device__ __forceinline__ void mma16816(float* c, const uint32_t* a, uint32_t b0, uint32_t b1) {
    asm volatile(
        "mma.sync.aligned.m16n8k16.row.col.f32.bf16.bf16.f32 "
        "{%0,%1,%2,%3}, {%4,%5,%6,%7}, {%8,%9}, {%0,%1,%2,%3};"
        : "+f"(c[0]), "+f"(c[1]), "+f"(c[2]), "+f"(c[3])
        : "r"(a[0]), "r"(a[1]), "r"(a[2]), "r"(a[3]), "r"(b0), "r"(b1));
}

__device__ __forceinline__ float fast_tanh(float x) {
    float xc = fminf(fmaxf(x, -12.0f), 12.0f);
    float e = __expf(2.0f * xc);
    return __fdividef(e - 1.0f, e + 1.0f);
}

__device__ __forceinline__ void split2(float x, uint32_t& hi, uint32_t& lo) {
    __nv_bfloat16 h = __float2bfloat16(x);
    __nv_bfloat16 l = __float2bfloat16(x - __bfloat162float(h));
    hi = (uint32_t)__bfloat16_as_ushort(h);
    lo = (uint32_t)__bfloat16_as_ushort(l);
}

// ------------------------- kernel 1: M = W + U, split to bf16 hi/lo -------------------------
__global__ void split_m_kernel(const float* __restrict__ W, const float* __restrict__ Um) {
    const size_t n4 = (size_t)Uu * Ee / 4;
    for (size_t i = (size_t)blockIdx.x * blockDim.x + threadIdx.x; i < n4;
         i += (size_t)gridDim.x * blockDim.x) {
        float4 w = ((const float4*)W)[i];
        float4 u = ((const float4*)Um)[i];
        float m[4] = {w.x + u.x, w.y + u.y, w.z + u.z, w.w + u.w};
        uint32_t hi[4], lo[4];
        #pragma unroll
        for (int j = 0; j < 4; j++) split2(m[j], hi[j], lo[j]);
        uint2 ph, pl;
        ph.x = (hi[1] << 16) | hi[0];  ph.y = (hi[3] << 16) | hi[2];
        pl.x = (lo[1] << 16) | lo[0];  pl.y = (lo[3] << 16) | lo[2];
        ((uint2*)g_Mhi)[i] = ph;
        ((uint2*)g_Mlo)[i] = pl;
    }
}

// ------------------------- kernel 2: fused split-bf16 GEMM + tanh + v-dot -------------------------
__global__ void __launch_bounds__(256, 1) gemm_score_kernel(const float* __restrict__ X,
                                                            const float* __restrict__ v) {
    extern __shared__ __align__(16) char dsm[];
    __shared__ float red[TM];

    const int tid  = threadIdx.x;
    const int wid  = tid >> 5;
    const int lane = tid & 31;
    const int wm   = wid & 1;   // 2 m-warps
    const int wn   = wid >> 1;  // 4 n-warps
    const int m0   = blockIdx.x * TM;

    const uint32_t ub = smem_u32(dsm);

    float ps[8];
    #pragma unroll
    for (int i = 0; i < 8; i++) ps[i] = 0.0f;

    for (int nc = 0; nc < NCH; ++nc) {
        const int n0 = nc * TN;
        float c[4][8][4];
        #pragma unroll
        for (int mf = 0; mf < 4; ++mf)
            #pragma unroll
            for (int nf = 0; nf < 8; ++nf)
                #pragma unroll
                for (int e = 0; e < 4; ++e) c[mf][nf][e] = 0.0f;

        // ---- stage fill lambdas (manual) ----
        // A: load X fp32, split to bf16 hi/lo, store to padded smem
        // B: cp.async pre-split bf16 from global
        // prologue: fill stage for kt=0 into buffer 0
        {
            char* sb = dsm;
            #pragma unroll
            for (int i = tid; i < TM * 8; i += 256) {      // 128 rows x 8 float4 chunks
                int r = i >> 3, cch = i & 7;
                float4 xv = *(const float4*)(X + (size_t)(m0 + r) * Ee + 0 * KT + cch * 4);
                float xs[4] = {xv.x, xv.y, xv.z, xv.w};
                uint32_t hi[4], lo[4];
                #pragma unroll
                for (int j = 0; j < 4; j++) split2(xs[j], hi[j], lo[j]);
                uint2 phh = make_uint2((hi[1] << 16) | hi[0], (hi[3] << 16) | hi[2]);
                uint2 pll = make_uint2((lo[1] << 16) | lo[0], (lo[3] << 16) | lo[2]);
                *(uint2*)(sb + SM_A_HI + r * ROWB + cch * 8) = phh;
                *(uint2*)(sb + SM_A_LO + r * ROWB + cch * 8) = pll;
            }
            #pragma unroll
            for (int i = tid; i < TN * 4 * 2; i += 256) {  // 256 rows x 4 chunks x {hi,lo}
                int arr = i >> 10, r = (i >> 2) & 255, cch = i & 3;
                const __nv_bfloat16* src =
                    (arr ? g_Mlo : g_Mhi) + (size_t)(n0 + r) * Ee + 0 * KT + cch * 8;
                uint32_t dst = ub + (arr ? SM_B_LO : SM_B_HI) + r * ROWB + cch * 16;
                cp_async16(dst, src);
            }
            cp_commit();
        }

        for (int kt = 0; kt < NKT; ++kt) {
            const int cur = kt & 1;
            // issue next stage loads
            if (kt + 1 < NKT) {
                const int k1 = (kt + 1) * KT;
                char* sb = dsm + (cur ^ 1) * STAGE;
                const uint32_t ubn = ub + (cur ^ 1) * STAGE;
                #pragma unroll
                for (int i = tid; i < TM * 8; i += 256) {
                    int r = i >> 3, cch = i & 7;
                    float4 xv = *(const float4*)(X + (size_t)(m0 + r) * Ee + k1 + cch * 4);
                    float xs[4] = {xv.x, xv.y, xv.z, xv.w};
                    uint32_t hi[4], lo[4];
                    #pragma unroll
                    for (int j = 0; j < 4; j++) split2(xs[j], hi[j], lo[j]);
                    uint2 phh = make_uint2((hi[1] << 16) | hi[0], (hi[3] << 16) | hi[2]);
                    uint2 pll = make_uint2((lo[1] << 16) | lo[0], (lo[3] << 16) | lo[2]);
                    *(uint2*)(sb + SM_A_HI + r * ROWB + cch * 8) = phh;
                    *(uint2*)(sb + SM_A_LO + r * ROWB + cch * 8) = pll;
                }
                #pragma unroll
                for (int i = tid; i < TN * 4 * 2; i += 256) {
                    int arr = i >> 10, r = (i >> 2) & 255, cch = i & 3;
                    const __nv_bfloat16* src =
                        (arr ? g_Mlo : g_Mhi) + (size_t)(n0 + r) * Ee + k1 + cch * 8;
                    uint32_t dst = ubn + (arr ? SM_B_LO : SM_B_HI) + r * ROWB + cch * 16;
                    cp_async16(dst, src);
                }
                cp_commit();
                asm volatile("cp.async.wait_group 1;" ::: "memory");
            } else {
                asm volatile("cp.async.wait_group 0;" ::: "memory");
            }
            __syncthreads();   // cur stage (A stores + B cp.async) visible to all warps

            // ---- MMA on cur stage: 2 x k16 steps, 3 precision terms ----
            const uint32_t sb = ub + cur * STAGE;
            #pragma unroll
            for (int kk = 0; kk < 2; ++kk) {
                #pragma unroll
                for (int t = 0; t < 3; ++t) {
                    const uint32_t aoff = (t == 1) ? SM_A_LO : SM_A_HI;
                    const uint32_t boff = (t == 2) ? SM_B_LO : SM_B_HI;
                    // A frags: 4 m-frags (16 rows each)
                    uint32_t a[4][4];
                    uint32_t abase = sb + aoff + (wm * 64 + (lane & 15)) * ROWB
                                   + kk * 32 + ((lane >> 4) << 4);
                    #pragma unroll
                    for (int mf = 0; mf < 4; ++mf)
                        ldsm_x4(a[mf], abase + mf * 16 * ROWB);
                    // B frags: 4 ldmatrix.x4, each covers 2 n-frags
                    uint32_t b[4][4];
                    uint32_t bbase = sb + boff
                                   + (wn * 64 + (lane & 7) + ((lane >> 4) << 3)) * ROWB
                                   + kk * 32 + ((lane & 8) << 1);
                    #pragma unroll
                    for (int nb = 0; nb < 4; ++nb)
                        ldsm_x4(b[nb], bbase + nb * 16 * ROWB);
                    #pragma unroll
                    for (int mf = 0; mf < 4; ++mf) {
                        #pragma unroll
                        for (int nb = 0; nb < 4; ++nb) {
                            mma16816(c[mf][2 * nb],     a[mf], b[nb][0], b[nb][1]);
                            mma16816(c[mf][2 * nb + 1], a[mf], b[nb][2], b[nb][3]);
                        }
                    }
                }
            }
            __syncthreads();   // all reads of cur done before it is refilled
        }

        // ---- epilogue: tanh(C) . v chunk into per-row partial scores ----
        #pragma unroll
        for (int mf = 0; mf < 4; ++mf) {
            #pragma unroll
            for (int nf = 0; nf < 8; ++nf) {
                int ncol = n0 + wn * 64 + nf * 8 + ((lane & 3) << 1);
                float v0 = __ldg(v + ncol);
                float v1 = __ldg(v + ncol + 1);
                ps[mf * 2 + 0] += fast_tanh(c[mf][nf][0]) * v0 + fast_tanh(c[mf][nf][1]) * v1;
                ps[mf * 2 + 1] += fast_tanh(c[mf][nf][2]) * v0 + fast_tanh(c[mf][nf][3]) * v1;
            }
        }
    }

    // ---- cross-lane + cross-warp score reduction ----
    #pragma unroll
    for (int i = 0; i < 8; i++) {
        ps[i] += __shfl_xor_sync(0xFFFFFFFFu, ps[i], 1);
        ps[i] += __shfl_xor_sync(0xFFFFFFFFu, ps[i], 2);
    }
    __syncthreads();
    if (tid < TM) red[tid] = 0.0f;
    __syncthreads();
    if ((lane & 3) == 0) {
        #pragma unroll
        for (int mf = 0; mf < 4; ++mf) {
            #pragma unroll
            for (int h = 0; h < 2; ++h) {
                int r = wm * 64 + mf * 16 + h * 8 + (lane >> 2);
                atomicAdd(&red[r], ps[mf * 2 + h]);
            }
        }
    }
    __syncthreads();
    if (tid < TM) g_score[m0 + tid] = red[tid];
}

// ------------------------- kernel 3: masked softmax over S per batch (+ zero out) -------------------------
__global__ void softmax_kernel(const int* __restrict__ mask, float* __restrict__ out) {
    const int b = blockIdx.x, tid = threadIdx.x;
    __shared__ float sh[Ss];
    __shared__ float red[256];

    for (int i = tid; i < Ee; i += 256) out[b * Ee + i] = 0.0f;  // zero for atomic out kernel

    float m = -1e30f;
    for (int s = tid; s < Ss; s += 256) {
        float sc = g_score[b * Ss + s];
        sc = (mask[b * Ss + s] != 0) ? sc : -1e30f;
        sh[s] = sc;
        m = fmaxf(m, sc);
    }
    red[tid] = m;
    __syncthreads();
    for (int o = 128; o > 0; o >>= 1) {
        if (tid < o) red[tid] = fmaxf(red[tid], red[tid + o]);
        __syncthreads();
    }
    const float mx = red[0];
    __syncthreads();

    float sum = 0.0f;
    for (int s = tid; s < Ss; s += 256) {
        float e = __expf(sh[s] - mx);   // masked rows underflow to 0
        sh[s] = e;
        sum += e;
    }
    red[tid] = sum;
    __syncthreads();
    for (int o = 128; o > 0; o >>= 1) {
        if (tid < o) red[tid] += red[tid + o];
        __syncthreads();
    }
    const float inv = 1.0f / red[0];
    for (int s = tid; s < Ss; s += 256) g_alpha[b * Ss + s] = sh[s] * inv;
}

// ------------------------- kernel 4: out[b,e] += sum_s alpha[b,s] * X[b,s,e] -------------------------
#define SSPLIT 8
#define SCHUNK (Ss / SSPLIT)   // 256
__global__ void out_kernel(const float* __restrict__ X, float* __restrict__ out) {
    const int b  = blockIdx.y;
    const int e  = blockIdx.x * 256 + threadIdx.x;
    const int s0 = blockIdx.z * SCHUNK;
    __shared__ float sa[SCHUNK];
    for (int s = threadIdx.x; s < SCHUNK; s += 256) sa[s] = g_alpha[b * Ss + s0 + s];
    __syncthreads();

    float acc = 0.0f;
    const float* xb = X + (size_t)b * Ss * Ee + (size_t)s0 * Ee + e;
    #pragma unroll 4
    for (int s = 0; s < SCHUNK; ++s) {
        float a = sa[s];
        if (a != 0.0f) acc += a * xb[(size_t)s * Ee];
    }
    atomicAdd(out + b * Ee + e, acc);
}

// ------------------------- launch -------------------------
extern "C" void kernel_launch(void* const* d_in, const int* in_sizes, int n_in,
                              void* d_out, int out_size) {
    const float* X    = (const float*)d_in[0];
    const int*   mask = (const int*)d_in[1];
    const float* W    = (const float*)d_in[2];
    const float* Um   = (const float*)d_in[3];
    const float* v    = (const float*)d_in[4];
    float* out = (float*)d_out;

    cudaFuncSetAttribute(gemm_score_kernel, cudaFuncAttributeMaxDynamicSharedMemorySize, SMEM_DYN);

    split_m_kernel<<<256, 256>>>(W, Um);
    gemm_score_kernel<<<TOK / TM, 256, SMEM_DYN>>>(X, v);
    softmax_kernel<<<Bb, 256>>>(mask, out);
    out_kernel<<<dim3(Ee / 256, Bb, SSPLIT), 256>>>(X, out);
}

// round 3
// speedup vs baseline: 1.0713x; 1.0713x over previous
#include <cuda_runtime.h>
#include <cuda_bf16.h>
#include <stdint.h>

// Problem dims
#define Bb   32
#define Ss   2048
#define Ee   1024
#define Uu   1024
#define TOK  (Bb * Ss)          // 65536 tokens

// GEMM tiling
#define TM   128                 // tokens per CTA
#define TN   256                 // U columns per n-chunk
#define KT   32                  // K tile (bf16 elements)
#define NCH  (Uu / TN)           // 4
#define NKT  (Ee / KT)           // 32

// Padded smem rows: 32 data halfs + 8 pad = 40 halfs = 80 bytes (conflict-free ldmatrix)
#define ROWB 80

// smem byte offsets within one stage
#define SM_A_HI 0
#define SM_A_LO (TM * ROWB)                  // 10240
#define SM_B_HI (2 * TM * ROWB)              // 20480
#define SM_B_LO (2 * TM * ROWB + TN * ROWB)  // 40960
#define STAGE   (2 * TM * ROWB + 2 * TN * ROWB)  // 61440
#define NSTAGE  3
#define SMEM_DYN (NSTAGE * STAGE)            // 184320

// ------------------------- device scratch -------------------------
__device__ __nv_bfloat16 g_Xhi[(size_t)TOK * Ee];   // 128 MB
__device__ __nv_bfloat16 g_Xlo[(size_t)TOK * Ee];   // 128 MB
__device__ __nv_bfloat16 g_Mhi[Uu * Ee];
__device__ __nv_bfloat16 g_Mlo[Uu * Ee];
__device__ float g_score[TOK];
__device__ float g_alpha[TOK];

// ------------------------- helpers -------------------------
__device__ __forceinline__ uint32_t smem_u32(const void* p) {
    uint32_t a;
    asm("{ .reg .u64 t; cvta.to.shared.u64 t, %1; cvt.u32.u64 %0, t; }"
        : "=r"(a) : "l"(p));
    return a;
}

__device__ __forceinline__ void cp_async16(uint32_t dst_smem, const void* src) {
    asm volatile("cp.async.ca.shared.global [%0], [%1], 16;"
                 :: "r"(dst_smem), "l"(src) : "memory");
}
__device__ __forceinline__ void cp_commit() {
    asm volatile("cp.async.commit_group;" ::: "memory");
}

__device__ __forceinline__ void ldsm_x4(uint32_t* r, uint32_t addr) {
    asm volatile("ldmatrix.sync.aligned.m8n8.x4.shared.b16 {%0,%1,%2,%3}, [%4];"
                 : "=r"(r[0]), "=r"(r[1]), "=r"(r[2]), "=r"(r[3]) : "r"(addr));
}

__device__ __forceinline__ void mma16816(float* c, const uint32_t* a, uint32_t b0, uint32_t b1) {
    asm volatile(
        "mma.sync.aligned.m16n8k16.row.col.f32.bf16.bf16.f32 "
        "{%0,%1,%2,%3}, {%4,%5,%6,%7}, {%8,%9}, {%0,%1,%2,%3};"
        : "+f"(c[0]), "+f"(c[1]), "+f"(c[2]), "+f"(c[3])
        : "r"(a[0]), "r"(a[1]), "r"(a[2]), "r"(a[3]), "r"(b0), "r"(b1));
}

__device__ __forceinline__ float fast_tanh(float x) {
    float xc = fminf(fmaxf(x, -12.0f), 12.0f);
    float e = __expf(2.0f * xc);
    return __fdividef(e - 1.0f, e + 1.0f);
}

__device__ __forceinline__ void split2(float x, uint32_t& hi, uint32_t& lo) {
    __nv_bfloat16 h = __float2bfloat16(x);
    __nv_bfloat16 l = __float2bfloat16(x - __bfloat162float(h));
    hi = (uint32_t)__bfloat16_as_ushort(h);
    lo = (uint32_t)__bfloat16_as_ushort(l);
}

// ------------------------- kernel 0: X -> bf16 hi/lo (one-shot) -------------------------
__global__ void conv_x_kernel(const float* __restrict__ X) {
    const size_t n4 = (size_t)TOK * Ee / 4;
    for (size_t i = (size_t)blockIdx.x * blockDim.x + threadIdx.x; i < n4;
         i += (size_t)gridDim.x * blockDim.x) {
        float4 xv = ((const float4*)X)[i];
        float xs[4] = {xv.x, xv.y, xv.z, xv.w};
        uint32_t hi[4], lo[4];
        #pragma unroll
        for (int j = 0; j < 4; j++) split2(xs[j], hi[j], lo[j]);
        uint2 ph, pl;
        ph.x = (hi[1] << 16) | hi[0];  ph.y = (hi[3] << 16) | hi[2];
        pl.x = (lo[1] << 16) | lo[0];  pl.y = (lo[3] << 16) | lo[2];
        ((uint2*)g_Xhi)[i] = ph;
        ((uint2*)g_Xlo)[i] = pl;
    }
}

// ------------------------- kernel 1: M = W + U, split to bf16 hi/lo -------------------------
__global__ void split_m_kernel(const float* __restrict__ W, const float* __restrict__ Um) {
    const size_t n4 = (size_t)Uu * Ee / 4;
    for (size_t i = (size_t)blockIdx.x * blockDim.x + threadIdx.x; i < n4;
         i += (size_t)gridDim.x * blockDim.x) {
        float4 w = ((const float4*)W)[i];
        float4 u = ((const float4*)Um)[i];
        float m[4] = {w.x + u.x, w.y + u.y, w.z + u.z, w.w + u.w};
        uint32_t hi[4], lo[4];
        #pragma unroll
        for (int j = 0; j < 4; j++) split2(m[j], hi[j], lo[j]);
        uint2 ph, pl;
        ph.x = (hi[1] << 16) | hi[0];  ph.y = (hi[3] << 16) | hi[2];
        pl.x = (lo[1] << 16) | lo[0];  pl.y = (lo[3] << 16) | lo[2];
        ((uint2*)g_Mhi)[i] = ph;
        ((uint2*)g_Mlo)[i] = pl;
    }
}

// ------------------------- kernel 2: fused split-bf16 GEMM + tanh + v-dot -------------------------
// All tile data arrives via cp.async (no generic smem stores, no conversion math in loop).
__global__ void __launch_bounds__(256, 1) gemm_score_kernel(const float* __restrict__ v) {
    extern __shared__ __align__(16) char dsm[];
    __shared__ float red[TM];

    const int tid  = threadIdx.x;
    const int wid  = tid >> 5;
    const int lane = tid & 31;
    const int wm   = wid & 1;   // 2 m-warps
    const int wn   = wid >> 1;  // 4 n-warps
    const int m0   = blockIdx.x * TM;

    const uint32_t ub = smem_u32(dsm);

    float ps[8];
    #pragma unroll
    for (int i = 0; i < 8; i++) ps[i] = 0.0f;

    // per-thread cp.async assignment (fixed across stages):
    //   A: 2 chunks  (TM*4*2 arrays = 1024 chunks / 256 threads = 4)  -> A_hi+A_lo: 4 chunks
    //   B: 8 chunks  (TN*4*2 = 2048 / 256)
    // decode once
    const int a_r0  = tid >> 1;            // 0..127 (2 threads per row, 2 chunks each? no:)
    // A chunks: i in [0, 1024): arr=i>>9, r=(i>>2)&127, c=i&3 ; thread does i=tid, tid+256, tid+512, tid+768
    // B chunks: i in [0, 2048): arr=i>>10, r=(i>>2)&255, c=i&3 ; thread does 8

    for (int nc = 0; nc < NCH; ++nc) {
        const int n0 = nc * TN;
        float c[4][8][4];
        #pragma unroll
        for (int mf = 0; mf < 4; ++mf)
            #pragma unroll
            for (int nf = 0; nf < 8; ++nf)
                #pragma unroll
                for (int e = 0; e < 4; ++e) c[mf][nf][e] = 0.0f;

        // ---- stage fill: pure cp.async ----
        auto fill_stage = [&](int kt, int buf) {
            const uint32_t sb = ub + buf * STAGE;
            const int k0 = kt * KT;
            #pragma unroll
            for (int i = tid; i < TM * 4 * 2; i += 256) {   // A hi/lo
                int arr = i >> 9, r = (i >> 2) & 127, cch = i & 3;
                const __nv_bfloat16* src =
                    (arr ? g_Xlo : g_Xhi) + (size_t)(m0 + r) * Ee + k0 + cch * 8;
                cp_async16(sb + (arr ? SM_A_LO : SM_A_HI) + r * ROWB + cch * 16, src);
            }
            #pragma unroll
            for (int i = tid; i < TN * 4 * 2; i += 256) {   // B hi/lo
                int arr = i >> 10, r = (i >> 2) & 255, cch = i & 3;
                const __nv_bfloat16* src =
                    (arr ? g_Mlo : g_Mhi) + (size_t)(n0 + r) * Ee + k0 + cch * 8;
                cp_async16(sb + (arr ? SM_B_LO : SM_B_HI) + r * ROWB + cch * 16, src);
            }
        };

        // prologue: stages 0 and 1
        __syncthreads();                 // prior nc reads / prior epilogue done
        fill_stage(0, 0); cp_commit();
        fill_stage(1, 1); cp_commit();

        for (int kt = 0; kt < NKT; ++kt) {
            __syncthreads();             // everyone done reading buf[(kt+2)%3] (iter kt-1)
            if (kt + 2 < NKT) fill_stage(kt + 2, (kt + 2) % NSTAGE);
            cp_commit();                 // unconditional: keeps group count uniform
            asm volatile("cp.async.wait_group 2;" ::: "memory");  // group kt complete
            __syncthreads();             // cross-thread visibility of stage kt

            const uint32_t sb = ub + (kt % NSTAGE) * STAGE;
            #pragma unroll
            for (int kk = 0; kk < 2; ++kk) {
                // A fragments (hi and lo), loaded once per kk
                uint32_t ah[4][4], al[4][4], b[4][4];
                uint32_t abase = sb + SM_A_HI + (wm * 64 + (lane & 15)) * ROWB
                               + kk * 32 + ((lane >> 4) << 4);
                #pragma unroll
                for (int mf = 0; mf < 4; ++mf) ldsm_x4(ah[mf], abase + mf * 16 * ROWB);
                #pragma unroll
                for (int mf = 0; mf < 4; ++mf) ldsm_x4(al[mf], abase + (SM_A_LO - SM_A_HI) + mf * 16 * ROWB);

                uint32_t bbase = sb + SM_B_HI
                               + (wn * 64 + (lane & 7) + ((lane >> 4) << 3)) * ROWB
                               + kk * 32 + ((lane & 8) << 1);
                // B_hi: terms hi*Bhi and lo*Bhi
                #pragma unroll
                for (int nb = 0; nb < 4; ++nb) ldsm_x4(b[nb], bbase + nb * 16 * ROWB);
                #pragma unroll
                for (int mf = 0; mf < 4; ++mf)
                    #pragma unroll
                    for (int nb = 0; nb < 4; ++nb) {
                        mma16816(c[mf][2 * nb],     ah[mf], b[nb][0], b[nb][1]);
                        mma16816(c[mf][2 * nb + 1], ah[mf], b[nb][2], b[nb][3]);
                    }
                #pragma unroll
                for (int mf = 0; mf < 4; ++mf)
                    #pragma unroll
                    for (int nb = 0; nb < 4; ++nb) {
                        mma16816(c[mf][2 * nb],     al[mf], b[nb][0], b[nb][1]);
                        mma16816(c[mf][2 * nb + 1], al[mf], b[nb][2], b[nb][3]);
                    }
                // B_lo: term hi*Blo
                #pragma unroll
                for (int nb = 0; nb < 4; ++nb)
                    ldsm_x4(b[nb], bbase + (SM_B_LO - SM_B_HI) + nb * 16 * ROWB);
                #pragma unroll
                for (int mf = 0; mf < 4; ++mf)
                    #pragma unroll
                    for (int nb = 0; nb < 4; ++nb) {
                        mma16816(c[mf][2 * nb],     ah[mf], b[nb][0], b[nb][1]);
                        mma16816(c[mf][2 * nb + 1], ah[mf], b[nb][2], b[nb][3]);
                    }
            }
        }

        // ---- epilogue: tanh(C) . v chunk into per-row partial scores ----
        #pragma unroll
        for (int mf = 0; mf < 4; ++mf) {
            #pragma unroll
            for (int nf = 0; nf < 8; ++nf) {
                int ncol = n0 + wn * 64 + nf * 8 + ((lane & 3) << 1);
                float v0 = __ldg(v + ncol);
                float v1 = __ldg(v + ncol + 1);
                ps[mf * 2 + 0] += fast_tanh(c[mf][nf][0]) * v0 + fast_tanh(c[mf][nf][1]) * v1;
                ps[mf * 2 + 1] += fast_tanh(c[mf][nf][2]) * v0 + fast_tanh(c[mf][nf][3]) * v1;
            }
        }
    }

    // ---- cross-lane + cross-warp score reduction ----
    #pragma unroll
    for (int i = 0; i < 8; i++) {
        ps[i] += __shfl_xor_sync(0xFFFFFFFFu, ps[i], 1);
        ps[i] += __shfl_xor_sync(0xFFFFFFFFu, ps[i], 2);
    }
    __syncthreads();
    if (tid < TM) red[tid] = 0.0f;
    __syncthreads();
    if ((lane & 3) == 0) {
        #pragma unroll
        for (int mf = 0; mf < 4; ++mf) {
            #pragma unroll
            for (int h = 0; h < 2; ++h) {
                int r = wm * 64 + mf * 16 + h * 8 + (lane >> 2);
                atomicAdd(&red[r], ps[mf * 2 + h]);
            }
        }
    }
    __syncthreads();
    if (tid < TM) g_score[m0 + tid] = red[tid];
}

// ------------------------- kernel 3: masked softmax over S per batch (+ zero out) -------------------------
__global__ void softmax_kernel(const int* __restrict__ mask, float* __restrict__ out) {
    const int b = blockIdx.x, tid = threadIdx.x;
    __shared__ float sh[Ss];
    __shared__ float red[256];

    for (int i = tid; i < Ee; i += 256) out[b * Ee + i] = 0.0f;  // zero for atomic out kernel

    float m = -1e30f;
    for (int s = tid; s < Ss; s += 256) {
        float sc = g_score[b * Ss + s];
        sc = (mask[b * Ss + s] != 0) ? sc : -1e30f;
        sh[s] = sc;
        m = fmaxf(m, sc);
    }
    red[tid] = m;
    __syncthreads();
    for (int o = 128; o > 0; o >>= 1) {
        if (tid < o) red[tid] = fmaxf(red[tid], red[tid + o]);
        __syncthreads();
    }
    const float mx = red[0];
    __syncthreads();

    float sum = 0.0f;
    for (int s = tid; s < Ss; s += 256) {
        float e = __expf(sh[s] - mx);   // masked rows underflow to 0
        sh[s] = e;
        sum += e;
    }
    red[tid] = sum;
    __syncthreads();
    for (int o = 128; o > 0; o >>= 1) {
        if (tid < o) red[tid] += red[tid + o];
        __syncthreads();
    }
    const float inv = 1.0f / red[0];
    for (int s = tid; s < Ss; s += 256) g_alpha[b * Ss + s] = sh[s] * inv;
}

// ------------------------- kernel 4: out[b,e] += sum_s alpha[b,s] * X[b,s,e] -------------------------
#define SSPLIT 16
#define SCHUNK (Ss / SSPLIT)   // 128
__global__ void out_kernel(const float* __restrict__ X, float* __restrict__ out) {
    const int b  = blockIdx.x;
    const int s0 = blockIdx.y * SCHUNK;
    const int tid = threadIdx.x;          // indexes float4 column, 256 x 4 = 1024
    __shared__ float sa[SCHUNK];
    if (tid < SCHUNK) sa[tid] = g_alpha[b * Ss + s0 + tid];
    __syncthreads();

    float4 acc = make_float4(0.f, 0.f, 0.f, 0.f);
    const float4* xb = (const float4*)(X + (size_t)b * Ss * Ee + (size_t)s0 * Ee) + tid;
    #pragma unroll 4
    for (int s = 0; s < SCHUNK; ++s) {
        float a = sa[s];
        if (a != 0.0f) {
            float4 x = xb[(size_t)s * (Ee / 4)];
            acc.x += a * x.x;  acc.y += a * x.y;
            acc.z += a * x.z;  acc.w += a * x.w;
        }
    }
    float* o = out + b * Ee + tid * 4;
    atomicAdd(o + 0, acc.x);
    atomicAdd(o + 1, acc.y);
    atomicAdd(o + 2, acc.z);
    atomicAdd(o + 3, acc.w);
}

// ------------------------- launch -------------------------
extern "C" void kernel_launch(void* const* d_in, const int* in_sizes, int n_in,
                              void* d_out, int out_size) {
    const float* X    = (const float*)d_in[0];
    const int*   mask = (const int*)d_in[1];
    const float* W    = (const float*)d_in[2];
    const float* Um   = (const float*)d_in[3];
    const float* v    = (const float*)d_in[4];
    float* out = (float*)d_out;

    cudaFuncSetAttribute(gemm_score_kernel, cudaFuncAttributeMaxDynamicSharedMemorySize, SMEM_DYN);

    conv_x_kernel<<<2048, 256>>>(X);
    split_m_kernel<<<256, 256>>>(W, Um);
    gemm_score_kernel<<<TOK / TM, 256, SMEM_DYN>>>(v);
    softmax_kernel<<<Bb, 256>>>(mask, out);
    out_kernel<<<dim3(Bb, SSPLIT), 256>>>(X, out);
}

// round 4
// speedup vs baseline: 1.4600x; 1.3629x over previous
#include <cuda_runtime.h>
#include <cuda_fp16.h>
#include <stdint.h>

// Problem dims
#define Bb   32
#define Ss   2048
#define Ee   1024
#define Uu   1024
#define TOK  (Bb * Ss)          // 65536 tokens

// GEMM tiling
#define TM   128                 // tokens per CTA
#define TN   256                 // U columns per n-chunk
#define KT   32                  // K tile (fp16 elements)
#define NCH  (Uu / TN)           // 4
#define NKT  (Ee / KT)           // 32

// Padded smem rows: 32 halfs + 8 pad = 40 halfs = 80 bytes (conflict-free ldmatrix)
#define ROWB 80

// smem byte offsets within one stage
#define SM_A_HI 0
#define SM_A_LO (TM * ROWB)                  // 10240
#define SM_B    (2 * TM * ROWB)              // 20480
#define STAGE   (2 * TM * ROWB + TN * ROWB)  // 40960
#define NSTAGE  4
#define SMEM_DYN (NSTAGE * STAGE)            // 163840

// ------------------------- device scratch -------------------------
__device__ __half g_Xhi[(size_t)TOK * Ee];   // 128 MB
__device__ __half g_Xlo[(size_t)TOK * Ee];   // 128 MB
__device__ __half g_Mh[Uu * Ee];             // 2 MB (L2-resident)
__device__ float g_score[TOK];
__device__ float g_alpha[TOK];

// ------------------------- helpers -------------------------
__device__ __forceinline__ uint32_t smem_u32(const void* p) {
    uint32_t a;
    asm("{ .reg .u64 t; cvta.to.shared.u64 t, %1; cvt.u32.u64 %0, t; }"
        : "=r"(a) : "l"(p));
    return a;
}

__device__ __forceinline__ void cp_async16(uint32_t dst_smem, const void* src) {
    asm volatile("cp.async.ca.shared.global [%0], [%1], 16;"
                 :: "r"(dst_smem), "l"(src) : "memory");
}
__device__ __forceinline__ void cp_commit() {
    asm volatile("cp.async.commit_group;" ::: "memory");
}

__device__ __forceinline__ void ldsm_x4(uint32_t* r, uint32_t addr) {
    asm volatile("ldmatrix.sync.aligned.m8n8.x4.shared.b16 {%0,%1,%2,%3}, [%4];"
                 : "=r"(r[0]), "=r"(r[1]), "=r"(r[2]), "=r"(r[3]) : "r"(addr));
}

__device__ __forceinline__ void mma16816(float* c, const uint32_t* a, uint32_t b0, uint32_t b1) {
    asm volatile(
        "mma.sync.aligned.m16n8k16.row.col.f32.f16.f16.f32 "
        "{%0,%1,%2,%3}, {%4,%5,%6,%7}, {%8,%9}, {%0,%1,%2,%3};"
        : "+f"(c[0]), "+f"(c[1]), "+f"(c[2]), "+f"(c[3])
        : "r"(a[0]), "r"(a[1]), "r"(a[2]), "r"(a[3]), "r"(b0), "r"(b1));
}

__device__ __forceinline__ float fast_tanh(float x) {
    float xc = fminf(fmaxf(x, -12.0f), 12.0f);
    float e = __expf(2.0f * xc);
    return __fdividef(e - 1.0f, e + 1.0f);
}

__device__ __forceinline__ void split2h(float x, uint32_t& hi, uint32_t& lo) {
    __half h = __float2half_rn(x);
    __half l = __float2half_rn(x - __half2float(h));
    hi = (uint32_t)__half_as_ushort(h);
    lo = (uint32_t)__half_as_ushort(l);
}

// ------------------------- kernel 0: X -> fp16 hi/lo (one-shot) -------------------------
__global__ void conv_x_kernel(const float* __restrict__ X) {
    const size_t n4 = (size_t)TOK * Ee / 4;
    for (size_t i = (size_t)blockIdx.x * blockDim.x + threadIdx.x; i < n4;
         i += (size_t)gridDim.x * blockDim.x) {
        float4 xv = ((const float4*)X)[i];
        float xs[4] = {xv.x, xv.y, xv.z, xv.w};
        uint32_t hi[4], lo[4];
        #pragma unroll
        for (int j = 0; j < 4; j++) split2h(xs[j], hi[j], lo[j]);
        uint2 ph, pl;
        ph.x = (hi[1] << 16) | hi[0];  ph.y = (hi[3] << 16) | hi[2];
        pl.x = (lo[1] << 16) | lo[0];  pl.y = (lo[3] << 16) | lo[2];
        ((uint2*)g_Xhi)[i] = ph;
        ((uint2*)g_Xlo)[i] = pl;
    }
}

// ------------------------- kernel 1: M = W + U -> fp16 -------------------------
__global__ void split_m_kernel(const float* __restrict__ W, const float* __restrict__ Um) {
    const size_t n4 = (size_t)Uu * Ee / 4;
    for (size_t i = (size_t)blockIdx.x * blockDim.x + threadIdx.x; i < n4;
         i += (size_t)gridDim.x * blockDim.x) {
        float4 w = ((const float4*)W)[i];
        float4 u = ((const float4*)Um)[i];
        float m[4] = {w.x + u.x, w.y + u.y, w.z + u.z, w.w + u.w};
        uint32_t h[4];
        #pragma unroll
        for (int j = 0; j < 4; j++) h[j] = (uint32_t)__half_as_ushort(__float2half_rn(m[j]));
        uint2 ph;
        ph.x = (h[1] << 16) | h[0];  ph.y = (h[3] << 16) | h[2];
        ((uint2*)g_Mh)[i] = ph;
    }
}

// ------------------------- kernel 2: fused 2-term fp16 GEMM + tanh + v-dot -------------------------
__global__ void __launch_bounds__(256, 1) gemm_score_kernel(const float* __restrict__ v) {
    extern __shared__ __align__(16) char dsm[];
    __shared__ float red[TM];

    const int tid  = threadIdx.x;
    const int wid  = tid >> 5;
    const int lane = tid & 31;
    const int wm   = wid & 1;   // 2 m-warps
    const int wn   = wid >> 1;  // 4 n-warps
    const int m0   = blockIdx.x * TM;

    const uint32_t ub = smem_u32(dsm);

    float ps[8];
    #pragma unroll
    for (int i = 0; i < 8; i++) ps[i] = 0.0f;

    for (int nc = 0; nc < NCH; ++nc) {
        const int n0 = nc * TN;
        float c[4][8][4];
        #pragma unroll
        for (int mf = 0; mf < 4; ++mf)
            #pragma unroll
            for (int nf = 0; nf < 8; ++nf)
                #pragma unroll
                for (int e = 0; e < 4; ++e) c[mf][nf][e] = 0.0f;

        // ---- stage fill: pure cp.async ----
        auto fill_stage = [&](int kt, int buf) {
            const uint32_t sb = ub + buf * STAGE;
            const int k0 = kt * KT;
            #pragma unroll
            for (int i = tid; i < TM * 4 * 2; i += 256) {   // A hi/lo: 1024 chunks
                int arr = i >> 9, r = (i >> 2) & 127, cch = i & 3;
                const __half* src =
                    (arr ? g_Xlo : g_Xhi) + (size_t)(m0 + r) * Ee + k0 + cch * 8;
                cp_async16(sb + (arr ? SM_A_LO : SM_A_HI) + r * ROWB + cch * 16, src);
            }
            #pragma unroll
            for (int i = tid; i < TN * 4; i += 256) {       // B: 1024 chunks
                int r = i >> 2, cch = i & 3;
                const __half* src = g_Mh + (size_t)(n0 + r) * Ee + k0 + cch * 8;
                cp_async16(sb + SM_B + r * ROWB + cch * 16, src);
            }
        };

        // prologue: stages 0..2
        __syncthreads();                 // prior nc reads / prior epilogue done
        fill_stage(0, 0); cp_commit();
        fill_stage(1, 1); cp_commit();
        fill_stage(2, 2); cp_commit();

        for (int kt = 0; kt < NKT; ++kt) {
            // fill kt+3 into buf (kt+3)%4 == (kt-1)%4 (read finished, synced at end of kt-1)
            if (kt + 3 < NKT) fill_stage(kt + 3, (kt + 3) % NSTAGE);
            cp_commit();                 // unconditional: uniform group count
            asm volatile("cp.async.wait_group 3;" ::: "memory");  // stage kt complete
            __syncthreads();             // cross-thread visibility of stage kt

            const uint32_t sb = ub + (kt % NSTAGE) * STAGE;
            #pragma unroll
            for (int kk = 0; kk < 2; ++kk) {
                uint32_t ah[4][4], al[4][4], b[4][4];
                uint32_t abase = sb + SM_A_HI + (wm * 64 + (lane & 15)) * ROWB
                               + kk * 32 + ((lane >> 4) << 4);
                #pragma unroll
                for (int mf = 0; mf < 4; ++mf) ldsm_x4(ah[mf], abase + mf * 16 * ROWB);
                #pragma unroll
                for (int mf = 0; mf < 4; ++mf)
                    ldsm_x4(al[mf], abase + (SM_A_LO - SM_A_HI) + mf * 16 * ROWB);

                uint32_t bbase = sb + SM_B
                               + (wn * 64 + (lane & 7) + ((lane >> 4) << 3)) * ROWB
                               + kk * 32 + ((lane & 8) << 1);
                #pragma unroll
                for (int nb = 0; nb < 4; ++nb) ldsm_x4(b[nb], bbase + nb * 16 * ROWB);

                // term 1: Ahi * B
                #pragma unroll
                for (int mf = 0; mf < 4; ++mf)
                    #pragma unroll
                    for (int nb = 0; nb < 4; ++nb) {
                        mma16816(c[mf][2 * nb],     ah[mf], b[nb][0], b[nb][1]);
                        mma16816(c[mf][2 * nb + 1], ah[mf], b[nb][2], b[nb][3]);
                    }
                // term 2: Alo * B
                #pragma unroll
                for (int mf = 0; mf < 4; ++mf)
                    #pragma unroll
                    for (int nb = 0; nb < 4; ++nb) {
                        mma16816(c[mf][2 * nb],     al[mf], b[nb][0], b[nb][1]);
                        mma16816(c[mf][2 * nb + 1], al[mf], b[nb][2], b[nb][3]);
                    }
            }
            __syncthreads();             // all reads of stage kt done before refill
        }

        // ---- epilogue: tanh(C) . v chunk into per-row partial scores ----
        #pragma unroll
        for (int mf = 0; mf < 4; ++mf) {
            #pragma unroll
            for (int nf = 0; nf < 8; ++nf) {
                int ncol = n0 + wn * 64 + nf * 8 + ((lane & 3) << 1);
                float v0 = __ldg(v + ncol);
                float v1 = __ldg(v + ncol + 1);
                ps[mf * 2 + 0] += fast_tanh(c[mf][nf][0]) * v0 + fast_tanh(c[mf][nf][1]) * v1;
                ps[mf * 2 + 1] += fast_tanh(c[mf][nf][2]) * v0 + fast_tanh(c[mf][nf][3]) * v1;
            }
        }
    }

    // ---- cross-lane + cross-warp score reduction ----
    #pragma unroll
    for (int i = 0; i < 8; i++) {
        ps[i] += __shfl_xor_sync(0xFFFFFFFFu, ps[i], 1);
        ps[i] += __shfl_xor_sync(0xFFFFFFFFu, ps[i], 2);
    }
    __syncthreads();
    if (tid < TM) red[tid] = 0.0f;
    __syncthreads();
    if ((lane & 3) == 0) {
        #pragma unroll
        for (int mf = 0; mf < 4; ++mf) {
            #pragma unroll
            for (int h = 0; h < 2; ++h) {
                int r = wm * 64 + mf * 16 + h * 8 + (lane >> 2);
                atomicAdd(&red[r], ps[mf * 2 + h]);
            }
        }
    }
    __syncthreads();
    if (tid < TM) g_score[m0 + tid] = red[tid];
}

// ------------------------- kernel 3: masked softmax over S per batch (+ zero out) -------------------------
__global__ void softmax_kernel(const int* __restrict__ mask, float* __restrict__ out) {
    const int b = blockIdx.x, tid = threadIdx.x;
    __shared__ float sh[Ss];
    __shared__ float red[256];

    for (int i = tid; i < Ee; i += 256) out[b * Ee + i] = 0.0f;  // zero for atomic out kernel

    float m = -1e30f;
    for (int s = tid; s < Ss; s += 256) {
        float sc = g_score[b * Ss + s];
        sc = (mask[b * Ss + s] != 0) ? sc : -1e30f;
        sh[s] = sc;
        m = fmaxf(m, sc);
    }
    red[tid] = m;
    __syncthreads();
    for (int o = 128; o > 0; o >>= 1) {
        if (tid < o) red[tid] = fmaxf(red[tid], red[tid + o]);
        __syncthreads();
    }
    const float mx = red[0];
    __syncthreads();

    float sum = 0.0f;
    for (int s = tid; s < Ss; s += 256) {
        float e = __expf(sh[s] - mx);   // masked rows underflow to 0
        sh[s] = e;
        sum += e;
    }
    red[tid] = sum;
    __syncthreads();
    for (int o = 128; o > 0; o >>= 1) {
        if (tid < o) red[tid] += red[tid + o];
        __syncthreads();
    }
    const float inv = 1.0f / red[0];
    for (int s = tid; s < Ss; s += 256) g_alpha[b * Ss + s] = sh[s] * inv;
}

// ------------------------- kernel 4: out[b,e] += sum_s alpha[b,s] * X[b,s,e] -------------------------
#define SSPLIT 16
#define SCHUNK (Ss / SSPLIT)   // 128
__global__ void out_kernel(const float* __restrict__ X, float* __restrict__ out) {
    const int b  = blockIdx.x;
    const int s0 = blockIdx.y * SCHUNK;
    const int tid = threadIdx.x;          // indexes float4 column, 256 x 4 = 1024
    __shared__ float sa[SCHUNK];
    if (tid < SCHUNK) sa[tid] = g_alpha[b * Ss + s0 + tid];
    __syncthreads();

    float4 acc = make_float4(0.f, 0.f, 0.f, 0.f);
    const float4* xb = (const float4*)(X + (size_t)b * Ss * Ee + (size_t)s0 * Ee) + tid;
    #pragma unroll 4
    for (int s = 0; s < SCHUNK; ++s) {
        float a = sa[s];
        if (a != 0.0f) {
            float4 x = xb[(size_t)s * (Ee / 4)];
            acc.x += a * x.x;  acc.y += a * x.y;
            acc.z += a * x.z;  acc.w += a * x.w;
        }
    }
    float* o = out + b * Ee + tid * 4;
    atomicAdd(o + 0, acc.x);
    atomicAdd(o + 1, acc.y);
    atomicAdd(o + 2, acc.z);
    atomicAdd(o + 3, acc.w);
}

// ------------------------- launch -------------------------
extern "C" void kernel_launch(void* const* d_in, const int* in_sizes, int n_in,
                              void* d_out, int out_size) {
    const float* X    = (const float*)d_in[0];
    const int*   mask = (const int*)d_in[1];
    const float* W    = (const float*)d_in[2];
    const float* Um   = (const float*)d_in[3];
    const float* v    = (const float*)d_in[4];
    float* out = (float*)d_out;

    cudaFuncSetAttribute(gemm_score_kernel, cudaFuncAttributeMaxDynamicSharedMemorySize, SMEM_DYN);

    conv_x_kernel<<<2048, 256>>>(X);
    split_m_kernel<<<256, 256>>>(W, Um);
    gemm_score_kernel<<<TOK / TM, 256, SMEM_DYN>>>(v);
    softmax_kernel<<<Bb, 256>>>(mask, out);
    out_kernel<<<dim3(Bb, SSPLIT), 256>>>(X, out);
}

// round 5
// speedup vs baseline: 2.1842x; 1.4960x over previous
#include <cuda_runtime.h>
#include <cuda_fp16.h>
#include <stdint.h>

// Problem dims
#define Bb   32
#define Ss   2048
#define Ee   1024
#define Uu   1024
#define TOK  (Bb * Ss)          // 65536 tokens

// GEMM tiling
#define TM   128                 // tokens per CTA
#define TN   256                 // U columns per n-chunk
#define KT   32                  // K tile (fp16 elements)
#define NCH  (Uu / TN)           // 4
#define NKT  (Ee / KT)           // 32
#define NIT  (NCH * NKT)         // 128 flattened k-iterations

// Padded smem rows: 32 halfs + 8 pad = 40 halfs = 80 bytes (conflict-free ldmatrix)
#define ROWB 80

// smem byte offsets within one stage
#define SM_A    0
#define SM_B    (TM * ROWB)                  // 10240
#define STAGE   (TM * ROWB + TN * ROWB)      // 30720
#define NSTAGE  5
#define SMEM_DYN (NSTAGE * STAGE)            // 153600

// ------------------------- device scratch -------------------------
__device__ __half g_Xh[(size_t)TOK * Ee];    // 128 MB
__device__ __half g_Mh[Uu * Ee];             // 2 MB (L2-resident)
__device__ float g_score[TOK];
__device__ float g_alpha[TOK];

// ------------------------- helpers -------------------------
__device__ __forceinline__ uint32_t smem_u32(const void* p) {
    uint32_t a;
    asm("{ .reg .u64 t; cvta.to.shared.u64 t, %1; cvt.u32.u64 %0, t; }"
        : "=r"(a) : "l"(p));
    return a;
}

__device__ __forceinline__ void cp_async16(uint32_t dst_smem, const void* src) {
    asm volatile("cp.async.ca.shared.global [%0], [%1], 16;"
                 :: "r"(dst_smem), "l"(src) : "memory");
}
__device__ __forceinline__ void cp_commit() {
    asm volatile("cp.async.commit_group;" ::: "memory");
}

__device__ __forceinline__ void ldsm_x4(uint32_t* r, uint32_t addr) {
    asm volatile("ldmatrix.sync.aligned.m8n8.x4.shared.b16 {%0,%1,%2,%3}, [%4];"
                 : "=r"(r[0]), "=r"(r[1]), "=r"(r[2]), "=r"(r[3]) : "r"(addr));
}

__device__ __forceinline__ void mma16816(float* c, const uint32_t* a, uint32_t b0, uint32_t b1) {
    asm volatile(
        "mma.sync.aligned.m16n8k16.row.col.f32.f16.f16.f32 "
        "{%0,%1,%2,%3}, {%4,%5,%6,%7}, {%8,%9}, {%0,%1,%2,%3};"
        : "+f"(c[0]), "+f"(c[1]), "+f"(c[2]), "+f"(c[3])
        : "r"(a[0]), "r"(a[1]), "r"(a[2]), "r"(a[3]), "r"(b0), "r"(b1));
}

__device__ __forceinline__ float fast_tanh(float x) {
    float xc = fminf(fmaxf(x, -12.0f), 12.0f);
    float e = __expf(2.0f * xc);
    return __fdividef(e - 1.0f, e + 1.0f);
}

// ------------------------- kernel 0: X -> fp16 (one-shot) -------------------------
__global__ void conv_x_kernel(const float* __restrict__ X) {
    const size_t n4 = (size_t)TOK * Ee / 4;
    for (size_t i = (size_t)blockIdx.x * blockDim.x + threadIdx.x; i < n4;
         i += (size_t)gridDim.x * blockDim.x) {
        float4 xv = ((const float4*)X)[i];
        uint32_t h[4];
        h[0] = (uint32_t)__half_as_ushort(__float2half_rn(xv.x));
        h[1] = (uint32_t)__half_as_ushort(__float2half_rn(xv.y));
        h[2] = (uint32_t)__half_as_ushort(__float2half_rn(xv.z));
        h[3] = (uint32_t)__half_as_ushort(__float2half_rn(xv.w));
        uint2 ph;
        ph.x = (h[1] << 16) | h[0];  ph.y = (h[3] << 16) | h[2];
        ((uint2*)g_Xh)[i] = ph;
    }
}

// ------------------------- kernel 1: M = W + U -> fp16 -------------------------
__global__ void split_m_kernel(const float* __restrict__ W, const float* __restrict__ Um) {
    const size_t n4 = (size_t)Uu * Ee / 4;
    for (size_t i = (size_t)blockIdx.x * blockDim.x + threadIdx.x; i < n4;
         i += (size_t)gridDim.x * blockDim.x) {
        float4 w = ((const float4*)W)[i];
        float4 u = ((const float4*)Um)[i];
        uint32_t h[4];
        h[0] = (uint32_t)__half_as_ushort(__float2half_rn(w.x + u.x));
        h[1] = (uint32_t)__half_as_ushort(__float2half_rn(w.y + u.y));
        h[2] = (uint32_t)__half_as_ushort(__float2half_rn(w.z + u.z));
        h[3] = (uint32_t)__half_as_ushort(__float2half_rn(w.w + u.w));
        uint2 ph;
        ph.x = (h[1] << 16) | h[0];  ph.y = (h[3] << 16) | h[2];
        ((uint2*)g_Mh)[i] = ph;
    }
}

// ------------------------- kernel 2: fused 1-term fp16 GEMM + tanh + v-dot -------------------------
__global__ void __launch_bounds__(256, 1) gemm_score_kernel(const float* __restrict__ v) {
    extern __shared__ __align__(16) char dsm[];
    __shared__ float red[TM];

    const int tid  = threadIdx.x;
    const int wid  = tid >> 5;
    const int lane = tid & 31;
    const int wm   = wid & 1;   // 2 m-warps
    const int wn   = wid >> 1;  // 4 n-warps
    const int m0   = blockIdx.x * TM;

    const uint32_t ub = smem_u32(dsm);

    float ps[8];
    #pragma unroll
    for (int i = 0; i < 8; i++) ps[i] = 0.0f;

    float c[4][8][4];
    #pragma unroll
    for (int mf = 0; mf < 4; ++mf)
        #pragma unroll
        for (int nf = 0; nf < 8; ++nf)
            #pragma unroll
            for (int e = 0; e < 4; ++e) c[mf][nf][e] = 0.0f;

    // ---- stage fill: pure cp.async; it indexes flattened (nc, kt) ----
    auto fill_stage = [&](int it, int buf) {
        const uint32_t sb = ub + buf * STAGE;
        const int k0 = (it & (NKT - 1)) * KT;
        const int n0 = (it >> 5) * TN;
        #pragma unroll
        for (int i = tid; i < TM * 4; i += 256) {       // A: 512 chunks, 2/thread
            int r = i >> 2, cch = i & 3;
            const __half* src = g_Xh + (size_t)(m0 + r) * Ee + k0 + cch * 8;
            cp_async16(sb + SM_A + r * ROWB + cch * 16, src);
        }
        #pragma unroll
        for (int i = tid; i < TN * 4; i += 256) {       // B: 1024 chunks, 4/thread
            int r = i >> 2, cch = i & 3;
            const __half* src = g_Mh + (size_t)(n0 + r) * Ee + k0 + cch * 8;
            cp_async16(sb + SM_B + r * ROWB + cch * 16, src);
        }
    };

    // prologue: stages 0..3 (groups 0..3)
    fill_stage(0, 0); cp_commit();
    fill_stage(1, 1); cp_commit();
    fill_stage(2, 2); cp_commit();
    fill_stage(3, 3); cp_commit();

    int buf_cur = 0, buf_fill = 4;
    #pragma unroll 1
    for (int it = 0; it < NIT; ++it) {
        asm volatile("cp.async.wait_group 3;" ::: "memory");  // stage it landed
        __syncthreads();   // publishes stage it AND retires all reads of stage it-1 buffer

        if (it + 4 < NIT) fill_stage(it + 4, buf_fill);
        cp_commit();       // unconditional: uniform group count
        buf_fill = (buf_fill + 1 == NSTAGE) ? 0 : buf_fill + 1;

        const uint32_t sb = ub + buf_cur * STAGE;
        buf_cur = (buf_cur + 1 == NSTAGE) ? 0 : buf_cur + 1;

        #pragma unroll
        for (int kk = 0; kk < 2; ++kk) {
            uint32_t a[4][4], b[4][4];
            uint32_t abase = sb + SM_A + (wm * 64 + (lane & 15)) * ROWB
                           + kk * 32 + ((lane >> 4) << 4);
            #pragma unroll
            for (int mf = 0; mf < 4; ++mf) ldsm_x4(a[mf], abase + mf * 16 * ROWB);

            uint32_t bbase = sb + SM_B
                           + (wn * 64 + (lane & 7) + ((lane >> 4) << 3)) * ROWB
                           + kk * 32 + ((lane & 8) << 1);
            #pragma unroll
            for (int nb = 0; nb < 4; ++nb) ldsm_x4(b[nb], bbase + nb * 16 * ROWB);

            #pragma unroll
            for (int mf = 0; mf < 4; ++mf)
                #pragma unroll
                for (int nb = 0; nb < 4; ++nb) {
                    mma16816(c[mf][2 * nb],     a[mf], b[nb][0], b[nb][1]);
                    mma16816(c[mf][2 * nb + 1], a[mf], b[nb][2], b[nb][3]);
                }
        }

        // ---- n-chunk epilogue (register-only; pipeline keeps flowing) ----
        if ((it & (NKT - 1)) == NKT - 1) {
            const int n0 = (it >> 5) * TN;
            #pragma unroll
            for (int mf = 0; mf < 4; ++mf) {
                #pragma unroll
                for (int nf = 0; nf < 8; ++nf) {
                    int ncol = n0 + wn * 64 + nf * 8 + ((lane & 3) << 1);
                    float v0 = __ldg(v + ncol);
                    float v1 = __ldg(v + ncol + 1);
                    ps[mf * 2 + 0] += fast_tanh(c[mf][nf][0]) * v0 + fast_tanh(c[mf][nf][1]) * v1;
                    ps[mf * 2 + 1] += fast_tanh(c[mf][nf][2]) * v0 + fast_tanh(c[mf][nf][3]) * v1;
                    #pragma unroll
                    for (int e = 0; e < 4; ++e) c[mf][nf][e] = 0.0f;
                }
            }
        }
    }

    // ---- cross-lane + cross-warp score reduction ----
    #pragma unroll
    for (int i = 0; i < 8; i++) {
        ps[i] += __shfl_xor_sync(0xFFFFFFFFu, ps[i], 1);
        ps[i] += __shfl_xor_sync(0xFFFFFFFFu, ps[i], 2);
    }
    __syncthreads();
    if (tid < TM) red[tid] = 0.0f;
    __syncthreads();
    if ((lane & 3) == 0) {
        #pragma unroll
        for (int mf = 0; mf < 4; ++mf) {
            #pragma unroll
            for (int h = 0; h < 2; ++h) {
                int r = wm * 64 + mf * 16 + h * 8 + (lane >> 2);
                atomicAdd(&red[r], ps[mf * 2 + h]);
            }
        }
    }
    __syncthreads();
    if (tid < TM) g_score[m0 + tid] = red[tid];
}

// ------------------------- kernel 3: masked softmax over S per batch (+ zero out) -------------------------
__global__ void softmax_kernel(const int* __restrict__ mask, float* __restrict__ out) {
    const int b = blockIdx.x, tid = threadIdx.x;
    __shared__ float sh[Ss];
    __shared__ float red[256];

    for (int i = tid; i < Ee; i += 256) out[b * Ee + i] = 0.0f;  // zero for atomic out kernel

    float m = -1e30f;
    for (int s = tid; s < Ss; s += 256) {
        float sc = g_score[b * Ss + s];
        sc = (mask[b * Ss + s] != 0) ? sc : -1e30f;
        sh[s] = sc;
        m = fmaxf(m, sc);
    }
    red[tid] = m;
    __syncthreads();
    for (int o = 128; o > 0; o >>= 1) {
        if (tid < o) red[tid] = fmaxf(red[tid], red[tid + o]);
        __syncthreads();
    }
    const float mx = red[0];
    __syncthreads();

    float sum = 0.0f;
    for (int s = tid; s < Ss; s += 256) {
        float e = __expf(sh[s] - mx);   // masked rows underflow to 0
        sh[s] = e;
        sum += e;
    }
    red[tid] = sum;
    __syncthreads();
    for (int o = 128; o > 0; o >>= 1) {
        if (tid < o) red[tid] += red[tid + o];
        __syncthreads();
    }
    const float inv = 1.0f / red[0];
    for (int s = tid; s < Ss; s += 256) g_alpha[b * Ss + s] = sh[s] * inv;
}

// ------------------------- kernel 4: out[b,e] += sum_s alpha[b,s] * X[b,s,e] -------------------------
#define SSPLIT 16
#define SCHUNK (Ss / SSPLIT)   // 128
__global__ void out_kernel(const float* __restrict__ X, float* __restrict__ out) {
    const int b  = blockIdx.x;
    const int s0 = blockIdx.y * SCHUNK;
    const int tid = threadIdx.x;          // indexes float4 column, 256 x 4 = 1024
    __shared__ float sa[SCHUNK];
    if (tid < SCHUNK) sa[tid] = g_alpha[b * Ss + s0 + tid];
    __syncthreads();

    float4 acc = make_float4(0.f, 0.f, 0.f, 0.f);
    const float4* xb = (const float4*)(X + (size_t)b * Ss * Ee + (size_t)s0 * Ee) + tid;
    #pragma unroll 4
    for (int s = 0; s < SCHUNK; ++s) {
        float a = sa[s];
        if (a != 0.0f) {
            float4 x = xb[(size_t)s * (Ee / 4)];
            acc.x += a * x.x;  acc.y += a * x.y;
            acc.z += a * x.z;  acc.w += a * x.w;
        }
    }
    float* o = out + b * Ee + tid * 4;
    atomicAdd(o + 0, acc.x);
    atomicAdd(o + 1, acc.y);
    atomicAdd(o + 2, acc.z);
    atomicAdd(o + 3, acc.w);
}

// ------------------------- launch -------------------------
extern "C" void kernel_launch(void* const* d_in, const int* in_sizes, int n_in,
                              void* d_out, int out_size) {
    const float* X    = (const float*)d_in[0];
    const int*   mask = (const int*)d_in[1];
    const float* W    = (const float*)d_in[2];
    const float* Um   = (const float*)d_in[3];
    const float* v    = (const float*)d_in[4];
    float* out = (float*)d_out;

    cudaFuncSetAttribute(gemm_score_kernel, cudaFuncAttributeMaxDynamicSharedMemorySize, SMEM_DYN);

    conv_x_kernel<<<2048, 256>>>(X);
    split_m_kernel<<<256, 256>>>(W, Um);
    gemm_score_kernel<<<TOK / TM, 256, SMEM_DYN>>>(v);
    softmax_kernel<<<Bb, 256>>>(mask, out);
    out_kernel<<<dim3(Bb, SSPLIT), 256>>>(X, out);
}